// round 13
// baseline (speedup 1.0000x reference)
#include <cuda_runtime.h>
#include <math_constants.h>

// Problem constants (fixed by the reference)
#define NM   32      // molecules
#define NA   40      // atoms per molecule
#define NSPEC 4
#define FEAT 384     // 4*16 + 10*32
#define RCR  5.2f
#define RCA  3.5f
#define BLK  128     // 4 warps, each owns one atom
#define FULL 0xFFFFFFFFu

__global__ __launch_bounds__(BLK)
void aev_kernel(const int* __restrict__ elem,
                const float* __restrict__ coords,
                float* __restrict__ out)
{
    const int tid  = threadIdx.x;
    const int lane = tid & 31;
    const int w    = tid >> 5;
    const int aid  = blockIdx.x * 4 + w;   // global atom id = m*NA + i
    const int m    = aid / NA;
    const int i    = aid % NA;

    // Warp-private compacted data (no cross-warp sharing, no __syncthreads)
    __shared__ float4 s_ag[4][NA];    // {dx, dy, dz, d}
    __shared__ float2 s_af[4][NA];    // {fcA, elem-as-float-bits}
    __shared__ float2 s_rd[4][NA];    // {d, fcR}, grouped by species

    float4* ag = s_ag[w];
    float2* af = s_af[w];
    float2* rd = s_rd[w];
    float*  o  = out + aid * FEAT;

    // ---- Angular per-lane constants ----
    const int at = lane >> 3;
    const int tt = lane & 7;
    const float shfa = 0.9f + 0.65f * (float)at;
    const float z = (CUDART_PI_F / 16.0f) * (float)(2*tt + 1);
    float sz, cz;
    __sincosf(z, &sz, &cz);

    // ---- Geometry + compaction (whole warp) ----
    const float xi = coords[aid*3 + 0];
    const float yi = coords[aid*3 + 1];
    const float zi = coords[aid*3 + 2];

    bool inR0=false, inA0=false, inR1=false, inA1=false;
    float dx0=0,dy0=0,dz0=0,d0=0,fA0=0,fR0=0;
    float dx1=0,dy1=0,dz1=0,d1=0,fA1=0,fR1=0;
    int   e0=0, e1v=0;
    {   // atom a0 = lane
        const float* cj = coords + (m*NA + lane)*3;
        dx0 = cj[0]-xi; dy0 = cj[1]-yi; dz0 = cj[2]-zi;
        d0  = sqrtf(dx0*dx0 + dy0*dy0 + dz0*dz0 + 1e-12f);
        fR0 = 0.5f * __cosf((CUDART_PI_F / RCR) * d0) + 0.5f;
        fA0 = 0.5f * __cosf((CUDART_PI_F / RCA) * d0) + 0.5f;
        e0  = elem[m*NA + lane];
        inR0 = (lane != i) && (d0 < RCR);
        inA0 = (lane != i) && (d0 < RCA);
    }
    if (lane < 8) {   // atom a1 = lane+32
        const int a1 = lane + 32;
        const float* cj = coords + (m*NA + a1)*3;
        dx1 = cj[0]-xi; dy1 = cj[1]-yi; dz1 = cj[2]-zi;
        d1  = sqrtf(dx1*dx1 + dy1*dy1 + dz1*dz1 + 1e-12f);
        fR1 = 0.5f * __cosf((CUDART_PI_F / RCR) * d1) + 0.5f;
        fA1 = 0.5f * __cosf((CUDART_PI_F / RCA) * d1) + 0.5f;
        e1v = elem[m*NA + a1];
        inR1 = (a1 != i) && (d1 < RCR);
        inA1 = (a1 != i) && (d1 < RCA);
    }

    // Angular compaction (ascending deterministic order)
    const unsigned bA0 = __ballot_sync(FULL, inA0);
    const unsigned bA1 = __ballot_sync(FULL, inA1);
    const unsigned lt  = (1u << lane) - 1u;
    if (inA0) {
        int p = __popc(bA0 & lt);
        ag[p] = make_float4(dx0, dy0, dz0, d0);
        af[p] = make_float2(fA0, __int_as_float(e0));
    }
    if (inA1) {
        int p = __popc(bA0) + __popc(bA1 & lt);
        ag[p] = make_float4(dx1, dy1, dz1, d1);
        af[p] = make_float2(fA1, __int_as_float(e1v));
    }

    // Radial compaction grouped by species; offsets stay in registers (uniform)
    unsigned bs0[NSPEC], bs1[NSPEC];
    #pragma unroll
    for (int s = 0; s < NSPEC; s++) {
        bs0[s] = __ballot_sync(FULL, inR0 && (e0  == s));
        bs1[s] = __ballot_sync(FULL, inR1 && (e1v == s));
    }
    int off[NSPEC + 1];
    off[0] = 0;
    #pragma unroll
    for (int s = 0; s < NSPEC; s++)
        off[s+1] = off[s] + __popc(bs0[s]) + __popc(bs1[s]);
    if (inR0) {
        int p = off[e0] + __popc(bs0[e0] & lt);
        rd[p] = make_float2(d0, fR0);
    }
    if (inR1) {
        int p = off[e1v] + __popc(bs0[e1v]) + __popc(bs1[e1v] & lt);
        rd[p] = make_float2(d1, fR1);
    }
    const int cntA = __popc(bA0) + __popc(bA1);
    const int np   = cntA * (cntA - 1) / 2;
    __syncwarp();

    // ---- Radial: lane owns features f = lane and f = lane+32 ----
    {
        const int fr = lane & 15;
        const float shf = 0.9f + 0.26875f * (float)fr;
        const int sA = lane >> 4;        // 0 or 1
        const int sB = sA + 2;           // 2 or 3
        float accA = 0.0f, accB = 0.0f;
        for (int n = off[sA]; n < off[sA+1]; n++) {
            float2 r = rd[n];
            float dd = r.x - shf;
            accA += 0.25f * __expf(-16.0f * dd * dd) * r.y;
        }
        for (int n = off[sB]; n < off[sB+1]; n++) {
            float2 r = rd[n];
            float dd = r.x - shf;
            accB += 0.25f * __expf(-16.0f * dd * dd) * r.y;
        }
        o[lane]      = accA;
        o[lane + 32] = accB;
    }

    // ---- Angular: rounds of 32 pairs; records exchanged via shuffle ----
    float acc[10];
    #pragma unroll
    for (int q = 0; q < 10; q++) acc[q] = 0.0f;

    for (int base = 0; base < np; base += 32) {
        const int n = min(32, np - base);
        float pc = 0.0f, psn = 0.0f, prm = 0.0f, pfc = 0.0f;
        int   ppidv = -1;
        if (lane < n) {
            const int q = base + lane;                 // global pair index
            int jj = 0, rem = q, row = cntA - 1;
            while (rem >= row) { rem -= row; row--; jj++; }
            int kk = jj + 1 + rem;
            const float4 gj = ag[jj], gk = ag[kk];
            const float2 fj = af[jj], fk = af[kk];
            float dot = gj.x*gk.x + gj.y*gk.y + gj.z*gk.z;
            float dj = gj.w, dk = gk.w;
            pc  = 0.95f * __fdividef(dot, dj * dk);    // |pc| <= 0.95
            psn = sqrtf(1.0f - pc*pc);                 // sin(acos(pc)) >= 0
            prm = 0.5f * (dj + dk);
            pfc = fj.x * fk.x;
            int ej = __float_as_int(fj.y), ek = __float_as_int(fk.y);
            int lo = min(ej, ek), hi = max(ej, ek);
            ppidv = lo*NSPEC - (lo*(lo-1))/2 + (hi - lo);
        }
        for (int p = 0; p < n; p++) {
            const float c   = __shfl_sync(FULL, pc,   p);
            const float sn  = __shfl_sync(FULL, psn,  p);
            const float rm  = __shfl_sync(FULL, prm,  p);
            const float fcp = __shfl_sync(FULL, pfc,  p);
            const int   pid = __shfl_sync(FULL, ppidv, p);
            float cth = c*cz + sn*sz;        // cos(theta - z)
            float x   = 0.5f + 0.5f*cth;
            float x2  = x*x;
            float x4  = x2*x2;
            float x8  = x4*x4;
            float x16 = x8*x8;
            float x32 = x16*x16;             // x^ZETA, ZETA=32
            float dr  = rm - shfa;
            float term = 2.0f * __expf(-8.0f * dr * dr) * x32 * fcp;
            #pragma unroll
            for (int q = 0; q < 10; q++)
                acc[q] += (pid == q) ? term : 0.0f;   // select-add, no branch
        }
    }

    // ---- Store angular: 10 coalesced 128B rows ----
    #pragma unroll
    for (int q = 0; q < 10; q++)
        o[64 + q*32 + lane] = acc[q];
}

extern "C" void kernel_launch(void* const* d_in, const int* in_sizes, int n_in,
                              void* d_out, int out_size)
{
    const int*   elem   = (const int*)  d_in[0];   // elem_idxs (M*A) int32
    const float* coords = (const float*)d_in[1];   // coords (M*A*3) float32
    float*       out    = (float*)d_out;           // (M*A*FEAT) float32
    (void)in_sizes; (void)n_in; (void)out_size;
    aev_kernel<<<(NM * NA) / 4, BLK>>>(elem, coords, out);
}

// round 14
// speedup vs baseline: 1.0472x; 1.0472x over previous
#include <cuda_runtime.h>
#include <math_constants.h>

// Problem constants (fixed by the reference)
#define NM   32      // molecules
#define NA   40      // atoms per molecule
#define NSPEC 4
#define FEAT 384     // 4*16 + 10*32
#define RCR  5.2f
#define RCA  3.5f
#define BLK  128
#define FULL 0xFFFFFFFFu

__global__ __launch_bounds__(BLK)
void aev_kernel(const int* __restrict__ elem,
                const float* __restrict__ coords,
                float* __restrict__ out)
{
    const int bid  = blockIdx.x;        // m*NA + i
    const int m    = bid / NA;
    const int i    = bid % NA;
    const int tid  = threadIdx.x;
    const int lane = tid & 31;
    const int w    = tid >> 5;

    // Compacted angular geometry (vectorized), built by warp 0
    __shared__ float4 s_ag[NA];         // {dx, dy, dz, d}
    __shared__ float2 s_af[NA];         // {fcA, elem-as-float-bits}
    // Radial records grouped by species; srOff[s]..srOff[s+1] = species-s segment
    __shared__ float2 s_rd[NA];         // {d, fcR}
    __shared__ int    srOff[5];
    __shared__ int    scntA;
    // Warp-private pair records (per 32-pair round)
    __shared__ float4 s_pd[4][32];
    __shared__ int    s_pidb[4][32];

    float* o = out + bid * FEAT;

    // ---- Angular per-lane setup (ALL warps, overlaps warp-0 prologue) ----
    const int at = lane >> 3;
    const int tt = lane & 7;
    const float shfa = 0.9f + 0.65f * (float)at;
    const float z = (CUDART_PI_F / 16.0f) * (float)(2*tt + 1);
    float sz, cz;
    __sincosf(z, &sz, &cz);

    // ---- Phase 1 (warp 0 only): geometry + species-sorted compaction ----
    if (w == 0) {
        const float xi = coords[(m*NA + i)*3 + 0];
        const float yi = coords[(m*NA + i)*3 + 1];
        const float zi = coords[(m*NA + i)*3 + 2];

        bool inR0=false, inA0=false, inR1=false, inA1=false;
        float dx0=0,dy0=0,dz0=0,d0=0,fA0=0,fR0=0;
        float dx1=0,dy1=0,dz1=0,d1=0,fA1=0,fR1=0;
        int   e0=0, e1v=0;
        {   // atom a0 = lane
            const float* cj = coords + (m*NA + lane)*3;
            dx0 = cj[0]-xi; dy0 = cj[1]-yi; dz0 = cj[2]-zi;
            d0  = sqrtf(dx0*dx0 + dy0*dy0 + dz0*dz0 + 1e-12f);
            fR0 = 0.5f * __cosf((CUDART_PI_F / RCR) * d0) + 0.5f;
            fA0 = 0.5f * __cosf((CUDART_PI_F / RCA) * d0) + 0.5f;
            e0  = elem[m*NA + lane];
            inR0 = (lane != i) && (d0 < RCR);
            inA0 = (lane != i) && (d0 < RCA);
        }
        if (lane < 8) {   // atom a1 = lane+32
            const int a1 = lane + 32;
            const float* cj = coords + (m*NA + a1)*3;
            dx1 = cj[0]-xi; dy1 = cj[1]-yi; dz1 = cj[2]-zi;
            d1  = sqrtf(dx1*dx1 + dy1*dy1 + dz1*dz1 + 1e-12f);
            fR1 = 0.5f * __cosf((CUDART_PI_F / RCR) * d1) + 0.5f;
            fA1 = 0.5f * __cosf((CUDART_PI_F / RCA) * d1) + 0.5f;
            e1v = elem[m*NA + a1];
            inR1 = (a1 != i) && (d1 < RCR);
            inA1 = (a1 != i) && (d1 < RCA);
        }

        // Angular compaction (ascending order)
        const unsigned bA0 = __ballot_sync(FULL, inA0);
        const unsigned bA1 = __ballot_sync(FULL, inA1);
        const unsigned lt  = (1u << lane) - 1u;
        if (inA0) {
            int p = __popc(bA0 & lt);
            s_ag[p] = make_float4(dx0, dy0, dz0, d0);
            s_af[p] = make_float2(fA0, __int_as_float(e0));
        }
        if (inA1) {
            int p = __popc(bA0) + __popc(bA1 & lt);
            s_ag[p] = make_float4(dx1, dy1, dz1, d1);
            s_af[p] = make_float2(fA1, __int_as_float(e1v));
        }

        // Radial compaction GROUPED BY SPECIES (per-species ballots)
        unsigned bs0[NSPEC], bs1[NSPEC];
        #pragma unroll
        for (int s = 0; s < NSPEC; s++) {
            bs0[s] = __ballot_sync(FULL, inR0 && (e0  == s));
            bs1[s] = __ballot_sync(FULL, inR1 && (e1v == s));
        }
        int off[NSPEC + 1];
        off[0] = 0;
        #pragma unroll
        for (int s = 0; s < NSPEC; s++)
            off[s+1] = off[s] + __popc(bs0[s]) + __popc(bs1[s]);
        if (inR0) {
            int p = off[e0] + __popc(bs0[e0] & lt);
            s_rd[p] = make_float2(d0, fR0);
        }
        if (inR1) {
            int p = off[e1v] + __popc(bs0[e1v]) + __popc(bs1[e1v] & lt);
            s_rd[p] = make_float2(d1, fR1);
        }
        if (lane < 5) srOff[lane] = off[lane];
        if (lane == 0) scntA = __popc(bA0) + __popc(bA1);
    }
    __syncthreads();

    const int cntA = scntA;
    const int np   = cntA * (cntA - 1) / 2;

    // ---- Radial features (warps 0,1): species-s segment only (~3 iters) ----
    if (w < 2) {
        const int f  = w*32 + lane;
        const int s  = f >> 4;
        const int fr = f & 15;
        const float shf = 0.9f + 0.26875f * (float)fr;
        const int n0 = srOff[s], n1 = srOff[s+1];
        float racc = 0.0f;
        #pragma unroll 2
        for (int n = n0; n < n1; n++) {
            float2 rd = s_rd[n];
            float dd = rd.x - shf;
            racc += 0.25f * __expf(-16.0f * dd * dd) * rd.y;
        }
        o[f] = racc;
    }

    // ---- Angular: EVERY warp scans ALL pairs; warp w owns pids {w, w+4, w+8}
    //      (redundant scan beats split-scan + combine for realistic np) ----
    float acc0 = 0.0f, acc1 = 0.0f, acc2 = 0.0f;
    const int q0 = w;                    // owned pid 0 (always < 10)
    const int q1 = w + 4;                // owned pid 1 (always < 10)
    const int q2 = w + 8;                // owned pid 2 (only valid for w<2)

    float4* pd   = s_pd[w];
    int*    pidb = s_pidb[w];

    for (int base = 0; base < np; base += 32) {
        const int n = min(32, np - base);
        if (lane < n) {
            const int q = base + lane;                 // global pair index
            int jj = 0, rem = q, row = cntA - 1;
            while (rem >= row) { rem -= row; row--; jj++; }
            int kk = jj + 1 + rem;
            const float4 gj = s_ag[jj], gk = s_ag[kk];
            const float2 fj = s_af[jj], fk = s_af[kk];
            float dot = gj.x*gk.x + gj.y*gk.y + gj.z*gk.z;
            float dj = gj.w, dk = gk.w;
            float c  = 0.95f * __fdividef(dot, dj * dk);  // |c| <= 0.95
            float sn = sqrtf(1.0f - c*c);                 // sin(acos(c)) >= 0
            pd[lane] = make_float4(c, sn, 0.5f*(dj + dk), fj.x*fk.x);
            int ej = __float_as_int(fj.y), ek = __float_as_int(fk.y);
            int lo = min(ej, ek), hi = max(ej, ek);
            pidb[lane] = lo*NSPEC - (lo*(lo-1))/2 + (hi - lo);
        }
        __syncwarp();
        #pragma unroll 4
        for (int p = 0; p < n; p++) {
            const int    pid = pidb[p];   // warp-uniform broadcast
            const float4 r   = pd[p];     // broadcast LDS.128
            float cth = r.x*cz + r.y*sz;  // cos(theta - z)
            float x   = 0.5f + 0.5f*cth;
            float x2  = x*x;
            float x4  = x2*x2;
            float x8  = x4*x4;
            float x16 = x8*x8;
            float x32 = x16*x16;          // x^ZETA, ZETA=32
            float dr  = r.z - shfa;
            float term = 2.0f * __expf(-8.0f * dr * dr) * x32 * r.w;
            acc0 += (pid == q0) ? term : 0.0f;            // select-add, no branch
            acc1 += (pid == q1) ? term : 0.0f;
            acc2 += (pid == q2) ? term : 0.0f;            // dead for w>=2 (q2>=10 never matches)
        }
        __syncwarp();
    }

    // ---- Store owned pid rows (coalesced 128B per row); no combine barrier ----
    o[64 + q0*32 + lane] = acc0;
    o[64 + q1*32 + lane] = acc1;
    if (q2 < 10)
        o[64 + q2*32 + lane] = acc2;
}

extern "C" void kernel_launch(void* const* d_in, const int* in_sizes, int n_in,
                              void* d_out, int out_size)
{
    const int*   elem   = (const int*)  d_in[0];   // elem_idxs (M*A) int32
    const float* coords = (const float*)d_in[1];   // coords (M*A*3) float32
    float*       out    = (float*)d_out;           // (M*A*FEAT) float32
    (void)in_sizes; (void)n_in; (void)out_size;
    aev_kernel<<<NM * NA, BLK>>>(elem, coords, out);
}

// round 15
// speedup vs baseline: 1.1851x; 1.1317x over previous
#include <cuda_runtime.h>
#include <math_constants.h>

// Problem constants (fixed by the reference)
#define NM   32      // molecules
#define NA   40      // atoms per molecule
#define NSPEC 4
#define FEAT 384     // 4*16 + 10*32
#define RCR  5.2f
#define RCA  3.5f
#define BLK  128
#define FULL 0xFFFFFFFFu

__global__ __launch_bounds__(BLK)
void aev_kernel(const int* __restrict__ elem,
                const float* __restrict__ coords,
                float* __restrict__ out)
{
    const int bid  = blockIdx.x;        // m*NA + i
    const int m    = bid / NA;
    const int i    = bid % NA;
    const int tid  = threadIdx.x;
    const int lane = tid & 31;
    const int w    = tid >> 5;

    // Compacted angular geometry (built by warp 0)
    __shared__ float4 s_ag[NA];         // {dx, dy, dz, d}
    __shared__ float2 s_af[NA];         // {fcA, elem-as-float-bits}
    // Radial records grouped by species (built by warp 1)
    __shared__ float2 s_rd[NA];         // {d, fcR}
    __shared__ int    srOff[5];
    __shared__ int    scntA;
    // Warp-private pair records (per 32-pair round)
    __shared__ float4 s_pd[4][32];
    __shared__ int    s_pidb[4][32];
    // Angular partials: [warp][pid][lane] (lane stride-1 -> conflict-free)
    __shared__ float  s_part[4][10][32];

    float* o = out + bid * FEAT;

    // ---- Angular per-lane setup (ALL warps, overlaps prologue) ----
    const int at = lane >> 3;
    const int tt = lane & 7;
    const float shfa = 0.9f + 0.65f * (float)at;
    const float z = (CUDART_PI_F / 16.0f) * (float)(2*tt + 1);
    float sz, cz;
    __sincosf(z, &sz, &cz);

    // ---- Prologue, SPLIT: warp 0 = angular side, warp 1 = radial side ----
    if (w == 0) {
        const float xi = coords[(m*NA + i)*3 + 0];
        const float yi = coords[(m*NA + i)*3 + 1];
        const float zi = coords[(m*NA + i)*3 + 2];

        bool inA0=false, inA1=false;
        float dx0=0,dy0=0,dz0=0,d0=0,fA0=0;
        float dx1=0,dy1=0,dz1=0,d1=0,fA1=0;
        int   e0=0, e1v=0;
        {   // atom a0 = lane
            const float* cj = coords + (m*NA + lane)*3;
            dx0 = cj[0]-xi; dy0 = cj[1]-yi; dz0 = cj[2]-zi;
            d0  = sqrtf(dx0*dx0 + dy0*dy0 + dz0*dz0 + 1e-12f);
            fA0 = 0.5f * __cosf((CUDART_PI_F / RCA) * d0) + 0.5f;
            e0  = elem[m*NA + lane];
            inA0 = (lane != i) && (d0 < RCA);
        }
        if (lane < 8) {   // atom a1 = lane+32
            const int a1 = lane + 32;
            const float* cj = coords + (m*NA + a1)*3;
            dx1 = cj[0]-xi; dy1 = cj[1]-yi; dz1 = cj[2]-zi;
            d1  = sqrtf(dx1*dx1 + dy1*dy1 + dz1*dz1 + 1e-12f);
            fA1 = 0.5f * __cosf((CUDART_PI_F / RCA) * d1) + 0.5f;
            e1v = elem[m*NA + a1];
            inA1 = (a1 != i) && (d1 < RCA);
        }
        const unsigned bA0 = __ballot_sync(FULL, inA0);
        const unsigned bA1 = __ballot_sync(FULL, inA1);
        const unsigned lt  = (1u << lane) - 1u;
        if (inA0) {
            int p = __popc(bA0 & lt);
            s_ag[p] = make_float4(dx0, dy0, dz0, d0);
            s_af[p] = make_float2(fA0, __int_as_float(e0));
        }
        if (inA1) {
            int p = __popc(bA0) + __popc(bA1 & lt);
            s_ag[p] = make_float4(dx1, dy1, dz1, d1);
            s_af[p] = make_float2(fA1, __int_as_float(e1v));
        }
        if (lane == 0) scntA = __popc(bA0) + __popc(bA1);
    } else if (w == 1) {
        const float xi = coords[(m*NA + i)*3 + 0];
        const float yi = coords[(m*NA + i)*3 + 1];
        const float zi = coords[(m*NA + i)*3 + 2];

        bool inR0=false, inR1=false;
        float d0=0, fR0=0, d1=0, fR1=0;
        int   e0=0, e1v=0;
        {   // atom a0 = lane
            const float* cj = coords + (m*NA + lane)*3;
            float dx = cj[0]-xi, dy = cj[1]-yi, dz = cj[2]-zi;
            d0  = sqrtf(dx*dx + dy*dy + dz*dz + 1e-12f);
            fR0 = 0.5f * __cosf((CUDART_PI_F / RCR) * d0) + 0.5f;
            e0  = elem[m*NA + lane];
            inR0 = (lane != i) && (d0 < RCR);
        }
        if (lane < 8) {   // atom a1 = lane+32
            const int a1 = lane + 32;
            const float* cj = coords + (m*NA + a1)*3;
            float dx = cj[0]-xi, dy = cj[1]-yi, dz = cj[2]-zi;
            d1  = sqrtf(dx*dx + dy*dy + dz*dz + 1e-12f);
            fR1 = 0.5f * __cosf((CUDART_PI_F / RCR) * d1) + 0.5f;
            e1v = elem[m*NA + a1];
            inR1 = (a1 != i) && (d1 < RCR);
        }
        const unsigned lt = (1u << lane) - 1u;
        unsigned bs0[NSPEC], bs1[NSPEC];
        #pragma unroll
        for (int s = 0; s < NSPEC; s++) {
            bs0[s] = __ballot_sync(FULL, inR0 && (e0  == s));
            bs1[s] = __ballot_sync(FULL, inR1 && (e1v == s));
        }
        int off[NSPEC + 1];
        off[0] = 0;
        #pragma unroll
        for (int s = 0; s < NSPEC; s++)
            off[s+1] = off[s] + __popc(bs0[s]) + __popc(bs1[s]);
        if (inR0) {
            int p = off[e0] + __popc(bs0[e0] & lt);
            s_rd[p] = make_float2(d0, fR0);
        }
        if (inR1) {
            int p = off[e1v] + __popc(bs0[e1v]) + __popc(bs1[e1v] & lt);
            s_rd[p] = make_float2(d1, fR1);
        }
        if (lane < 5) srOff[lane] = off[lane];
    }
    __syncthreads();

    const int cntA = scntA;
    const int np   = cntA * (cntA - 1) / 2;

    // ---- Radial features (warps 0,1): species-s segment only (~3 iters) ----
    if (w < 2) {
        const int f  = w*32 + lane;
        const int s  = f >> 4;
        const int fr = f & 15;
        const float shf = 0.9f + 0.26875f * (float)fr;
        const int n0 = srOff[s], n1 = srOff[s+1];
        float racc = 0.0f;
        #pragma unroll 2
        for (int n = n0; n < n1; n++) {
            float2 rd = s_rd[n];
            float dd = rd.x - shf;
            racc += 0.25f * __expf(-16.0f * dd * dd) * rd.y;
        }
        o[f] = racc;
    }

    // ---- Angular: warp w owns global pairs q = w, w+4, w+8, ... ----
    float acc[10];
    #pragma unroll
    for (int q = 0; q < 10; q++) acc[q] = 0.0f;

    const int nloc = (np > w) ? (np - w + 3) >> 2 : 0;   // ceil((np-w)/4)
    float4* pd   = s_pd[w];
    int*    pidb = s_pidb[w];

    for (int lbase = 0; lbase < nloc; lbase += 32) {
        const int n = min(32, nloc - lbase);
        if (lane < n) {
            const int q = w + 4*(lbase + lane);          // global pair index
            // Closed-form triangular decode: no serial while-loop
            const int r = np - 1 - q;
            const int t = (int)((sqrtf((float)(8*r + 1)) - 1.0f) * 0.5f);
            const int jj = cntA - 2 - t;
            const int kk = cntA - 1 - (r - ((t*(t+1)) >> 1));
            const float4 gj = s_ag[jj], gk = s_ag[kk];
            const float2 fj = s_af[jj], fk = s_af[kk];
            float dot = gj.x*gk.x + gj.y*gk.y + gj.z*gk.z;
            float dj = gj.w, dk = gk.w;
            float c  = 0.95f * __fdividef(dot, dj * dk); // |c| <= 0.95
            float sn = sqrtf(1.0f - c*c);                // sin(acos(c)) >= 0
            pd[lane] = make_float4(c, sn, 0.5f*(dj + dk), fj.x*fk.x);
            int ej = __float_as_int(fj.y), ek = __float_as_int(fk.y);
            int lo = min(ej, ek), hi = max(ej, ek);
            pidb[lane] = lo*NSPEC - (lo*(lo-1))/2 + (hi - lo);
        }
        __syncwarp();
        #pragma unroll 4
        for (int p = 0; p < n; p++) {
            const int    pid = pidb[p];   // warp-uniform broadcast
            const float4 r   = pd[p];     // broadcast LDS.128
            float cth = r.x*cz + r.y*sz;  // cos(theta - z)
            float x   = 0.5f + 0.5f*cth;
            float x2  = x*x;
            float x4  = x2*x2;
            float x8  = x4*x4;
            float x16 = x8*x8;
            float x32 = x16*x16;          // x^ZETA, ZETA=32
            float dr  = r.z - shfa;
            float term = 2.0f * __expf(-8.0f * dr * dr) * x32 * r.w;
            #pragma unroll
            for (int q = 0; q < 10; q++)
                acc[q] += (pid == q) ? term : 0.0f;      // select-add, no branch
        }
        __syncwarp();
    }

    // ---- Write partials, balanced barrier, combine + store ----
    #pragma unroll
    for (int q = 0; q < 10; q++) s_part[w][q][lane] = acc[q];
    __syncthreads();

    // warp w reduces pids {w, w+4, w+8<10}
    #pragma unroll
    for (int q = w; q < 10; q += 4) {
        float v = s_part[0][q][lane] + s_part[1][q][lane]
                + s_part[2][q][lane] + s_part[3][q][lane];
        o[64 + q*32 + lane] = v;
    }
}

extern "C" void kernel_launch(void* const* d_in, const int* in_sizes, int n_in,
                              void* d_out, int out_size)
{
    const int*   elem   = (const int*)  d_in[0];   // elem_idxs (M*A) int32
    const float* coords = (const float*)d_in[1];   // coords (M*A*3) float32
    float*       out    = (float*)d_out;           // (M*A*FEAT) float32
    (void)in_sizes; (void)n_in; (void)out_size;
    aev_kernel<<<NM * NA, BLK>>>(elem, coords, out);
}